// round 11
// baseline (speedup 1.0000x reference)
#include <cuda_runtime.h>
#include <math.h>

// LocalHolder2D: out = sum_i w_i * log10(maxpool_k(x)), k = 3,5,7
// x: (B=8, C=64, H=256, W=256) fp32, strictly positive.
// Centered OLS weights (sum w_i = 0) -> log10(1/(H*W)) offset cancels.
//
// R11 = R5 inner loop EXACTLY (128-reg schedule, register ring, row-per-warp,
// VIMNMX3 int-domain max tree, 12 shuffles/row), repackaged as ONE-WARP
// BLOCKS: 4096 blocks x 32 threads, task = blockIdx. With 128 regs the SM
// holds 16 one-warp blocks (64K regs) and refills them individually as they
// finish -> no 4-warp wave quantization, sustained ~16 warps/SM instead of
// ~13. Inner loop untouched: R6 (smem ring) and R8 (reg squeeze) both showed
// the 128-reg register-ring schedule is load-bearing.

#define HH 256
#define WW 256
#define RPB 32                 /* rows per warp-task */
#define THREADS 32
#define NEG_I ((int)0xff800000)   /* -inf bits */

static __device__ __forceinline__ int imax2(int a, int b) { return a > b ? a : b; }

__global__ __launch_bounds__(THREADS, 16)
void holder_kernel(const int* __restrict__ x, float* __restrict__ out,
                   float w3, float w5, float w7)
{
    const int lane = threadIdx.x & 31;
    const int task = blockIdx.x;                    // 4096 tasks
    const int plane = task >> 3;
    const int y0 = (task & 7) * RPB;                // multiple of 8

    const int* __restrict__ src = x   + (size_t)plane * (HH * WW) + lane * 8;
    float*     __restrict__ dst = out + (size_t)plane * (HH * WW) + lane * 8;

    const unsigned FULL = 0xffffffffu;
    const bool l0 = (lane == 0), l31 = (lane == 31);

    // ring[slot][col]; slot for row r is r & 7 (y0 % 8 == 0).
    int ring[8][8];

    // Prologue: rows y0-3 .. y0+3 -> slots (j+5)&7 for j=0..6.
    #pragma unroll
    for (int j = 0; j < 7; ++j) {
        const int row = y0 - 3 + j;
        const int s = (j + 5) & 7;
        if (row >= 0) {
            const int4* rp = (const int4*)(src + row * WW);
            int4 a = rp[0], b = rp[1];
            ring[s][0] = a.x; ring[s][1] = a.y; ring[s][2] = a.z; ring[s][3] = a.w;
            ring[s][4] = b.x; ring[s][5] = b.y; ring[s][6] = b.z; ring[s][7] = b.w;
        } else {
            #pragma unroll
            for (int t = 0; t < 8; ++t) ring[s][t] = NEG_I;
        }
    }

    for (int ib = 0; ib < RPB; ib += 8) {
        #pragma unroll
        for (int u = 0; u < 8; ++u) {
            const int y = y0 + ib + u;            // output row; y & 7 == u
            // Prefetch row y+4 into slot (u+4)&7 (vacated row y-4).
            {
                const int row = y + 4;
                const int s = (u + 4) & 7;
                if (row < HH) {
                    const int4* rp = (const int4*)(src + row * WW);
                    int4 a = rp[0], b = rp[1];
                    ring[s][0] = a.x; ring[s][1] = a.y; ring[s][2] = a.z; ring[s][3] = a.w;
                    ring[s][4] = b.x; ring[s][5] = b.y; ring[s][6] = b.z; ring[s][7] = b.w;
                } else {
                    #pragma unroll
                    for (int t = 0; t < 8; ++t) ring[s][t] = NEG_I;
                }
            }

            int v[8];
            float acc[8];

            // ---- k = 3 ----
            #pragma unroll
            for (int j = 0; j < 8; ++j)
                v[j] = __vimax3_s32(ring[(u + 7) & 7][j], ring[u][j],
                                    ring[(u + 1) & 7][j]);
            {
                int L = __shfl_up_sync  (FULL, v[7], 1); if (l0)  L = NEG_I;
                int R = __shfl_down_sync(FULL, v[0], 1); if (l31) R = NEG_I;
                int m0 = __vimax3_s32(L, v[0], v[1]);
                int m7 = __vimax3_s32(v[6], v[7], R);
                acc[0] = w3 * __log2f(__int_as_float(m0));
                #pragma unroll
                for (int j = 1; j < 7; ++j)
                    acc[j] = w3 * __log2f(__int_as_float(
                                 __vimax3_s32(v[j - 1], v[j], v[j + 1])));
                acc[7] = w3 * __log2f(__int_as_float(m7));
            }

            // ---- k = 5 ----
            #pragma unroll
            for (int j = 0; j < 8; ++j)
                v[j] = __vimax3_s32(v[j], ring[(u + 6) & 7][j],
                                    ring[(u + 2) & 7][j]);
            {
                int p01 = imax2(v[0], v[1]), p23 = imax2(v[2], v[3]);
                int p45 = imax2(v[4], v[5]), p67 = imax2(v[6], v[7]);
                int Lp = __shfl_up_sync  (FULL, p67, 1);
                int L7 = __shfl_up_sync  (FULL, v[7], 1);
                int R0 = __shfl_down_sync(FULL, v[0], 1);
                int Rp = __shfl_down_sync(FULL, p01, 1);
                if (l0)  { Lp = NEG_I; L7 = NEG_I; }
                if (l31) { R0 = NEG_I; Rp = NEG_I; }
                int m[8];
                m[0] = __vimax3_s32(Lp,  p01, v[2]);
                m[1] = __vimax3_s32(L7,  p01, p23);
                m[2] = __vimax3_s32(p01, p23, v[4]);
                m[3] = __vimax3_s32(v[1], p23, p45);
                m[4] = __vimax3_s32(p23, p45, v[6]);
                m[5] = __vimax3_s32(v[3], p45, p67);
                m[6] = __vimax3_s32(p45, p67, R0);
                m[7] = __vimax3_s32(v[5], p67, Rp);
                #pragma unroll
                for (int j = 0; j < 8; ++j)
                    acc[j] = fmaf(w5, __log2f(__int_as_float(m[j])), acc[j]);
            }

            // ---- k = 7 ----
            #pragma unroll
            for (int j = 0; j < 8; ++j)
                v[j] = __vimax3_s32(v[j], ring[(u + 5) & 7][j],
                                    ring[(u + 3) & 7][j]);
            {
                int p01 = imax2(v[0], v[1]), p23 = imax2(v[2], v[3]);
                int p45 = imax2(v[4], v[5]), p67 = imax2(v[6], v[7]);
                int a03 = imax2(p01, p23),   a47 = imax2(p45, p67);
                int suf3 = imax2(v[5], p67); // cols 5..7
                int pre3 = imax2(p01, v[2]); // cols 0..2
                int Ls  = __shfl_up_sync  (FULL, suf3, 1);
                int Lq  = __shfl_up_sync  (FULL, p67, 1);
                int L7v = __shfl_up_sync  (FULL, v[7], 1);
                int R0v = __shfl_down_sync(FULL, v[0], 1);
                int Rq  = __shfl_down_sync(FULL, p01, 1);
                int Rp3 = __shfl_down_sync(FULL, pre3, 1);
                if (l0)  { Ls = NEG_I; Lq = NEG_I; L7v = NEG_I; }
                if (l31) { R0v = NEG_I; Rq = NEG_I; Rp3 = NEG_I; }
                int m[8];
                m[0] = imax2(Ls, a03);               // -3..3
                m[1] = __vimax3_s32(Lq,  a03, v[4]); // -2..4
                m[2] = __vimax3_s32(L7v, a03, p45);  // -1..5
                m[3] = __vimax3_s32(a03, p45, v[6]); //  0..6
                m[4] = __vimax3_s32(v[1], p23, a47); //  1..7
                m[5] = __vimax3_s32(p23, a47, R0v);  //  2..8
                m[6] = __vimax3_s32(v[3], a47, Rq);  //  3..9
                m[7] = imax2(a47, Rp3);              //  4..10
                #pragma unroll
                for (int j = 0; j < 8; ++j)
                    acc[j] = fmaf(w7, __log2f(__int_as_float(m[j])), acc[j]);
            }

            float* dp = dst + y * WW;
            ((float4*)dp)[0] = make_float4(acc[0], acc[1], acc[2], acc[3]);
            ((float4*)dp)[1] = make_float4(acc[4], acc[5], acc[6], acc[7]);
        }
    }
}

extern "C" void kernel_launch(void* const* d_in, const int* in_sizes, int n_in,
                              void* d_out, int out_size)
{
    const int* x = (const int*)d_in[0];
    float* out = (float*)d_out;

    const int planes = in_sizes[0] / (HH * WW);     // 512

    // Closed-form OLS slope weights (double on host); fold in log10(2).
    double l3 = log10(3.0), l5 = log10(5.0), l7 = log10(7.0);
    double mean = (l3 + l5 + l7) / 3.0;
    double c3 = l3 - mean, c5 = l5 - mean, c7 = l7 - mean;
    double s = c3 * c3 + c5 * c5 + c7 * c7;
    double L10_2 = 0.30102999566398119521;
    float w3 = (float)((c3 / s) * L10_2);
    float w5 = (float)((c5 / s) * L10_2);
    float w7 = (float)((c7 / s) * L10_2);

    const int tasks = planes * (HH / RPB);          // 4096
    dim3 grid(tasks);                               // one warp per block
    dim3 block(THREADS);
    holder_kernel<<<grid, block>>>(x, out, w3, w5, w7);
}

// round 12
// speedup vs baseline: 1.1076x; 1.1076x over previous
#include <cuda_runtime.h>
#include <math.h>

// LocalHolder2D: out = sum_i w_i * log10(maxpool_k(x)), k = 3,5,7
// x: (B=8, C=64, H=256, W=256) fp32, strictly positive.
// Centered OLS weights (sum w_i = 0) -> log10(1/(H*W)) offset cancels.
//
// R12 = R11 (one-warp blocks, register ring, row-per-warp, VIMNMX3 int-domain
// max tree, 12 shuffles/row — inner loop untouched, it is load-bearing)
// + prefetch.global.L2 of row y+12 each iteration. The 8-slot ring caps
// demand-load slack at 1 iteration (~235 cyc) < DRAM latency (~600 cyc) ->
// ~365 stall cyc/iter (measured issue=47%). Prefetching 8 iterations ahead
// turns the demand LDG into an L2 hit (~250 cyc), which the existing slack
// covers. One extra warp-inst per iteration, zero registers.

#define HH 256
#define WW 256
#define RPB 32                 /* rows per warp-task */
#define THREADS 32
#define NEG_I ((int)0xff800000)   /* -inf bits */
#define PFD 12                 /* prefetch distance in rows */

static __device__ __forceinline__ int imax2(int a, int b) { return a > b ? a : b; }

static __device__ __forceinline__ void l2_prefetch(const int* p) {
    asm volatile("prefetch.global.L2 [%0];" :: "l"(p));
}

__global__ __launch_bounds__(THREADS, 16)
void holder_kernel(const int* __restrict__ x, float* __restrict__ out,
                   float w3, float w5, float w7)
{
    const int lane = threadIdx.x & 31;
    const int task = blockIdx.x;                    // 4096 tasks
    const int plane = task >> 3;
    const int y0 = (task & 7) * RPB;                // multiple of 8

    const int* __restrict__ src = x   + (size_t)plane * (HH * WW) + lane * 8;
    float*     __restrict__ dst = out + (size_t)plane * (HH * WW) + lane * 8;

    const unsigned FULL = 0xffffffffu;
    const bool l0 = (lane == 0), l31 = (lane == 31);

    // ring[slot][col]; slot for row r is r & 7 (y0 % 8 == 0).
    int ring[8][8];

    // Prologue prefetch: rows y0+4 .. y0+PFD-1 (the gap the steady-state
    // prefetcher hasn't covered yet).
    #pragma unroll
    for (int j = 4; j < PFD; ++j) {
        const int row = y0 + j;
        if (row < HH) l2_prefetch(src + row * WW);
    }

    // Prologue: rows y0-3 .. y0+3 -> slots (j+5)&7 for j=0..6.
    #pragma unroll
    for (int j = 0; j < 7; ++j) {
        const int row = y0 - 3 + j;
        const int s = (j + 5) & 7;
        if (row >= 0) {
            const int4* rp = (const int4*)(src + row * WW);
            int4 a = rp[0], b = rp[1];
            ring[s][0] = a.x; ring[s][1] = a.y; ring[s][2] = a.z; ring[s][3] = a.w;
            ring[s][4] = b.x; ring[s][5] = b.y; ring[s][6] = b.z; ring[s][7] = b.w;
        } else {
            #pragma unroll
            for (int t = 0; t < 8; ++t) ring[s][t] = NEG_I;
        }
    }

    for (int ib = 0; ib < RPB; ib += 8) {
        #pragma unroll
        for (int u = 0; u < 8; ++u) {
            const int y = y0 + ib + u;            // output row; y & 7 == u
            // L2 prefetch far ahead (covers the whole 1KB row in one inst).
            {
                const int prow = y + PFD;
                if (prow < HH) l2_prefetch(src + prow * WW);
            }
            // Prefetch row y+4 into slot (u+4)&7 (vacated row y-4).
            {
                const int row = y + 4;
                const int s = (u + 4) & 7;
                if (row < HH) {
                    const int4* rp = (const int4*)(src + row * WW);
                    int4 a = rp[0], b = rp[1];
                    ring[s][0] = a.x; ring[s][1] = a.y; ring[s][2] = a.z; ring[s][3] = a.w;
                    ring[s][4] = b.x; ring[s][5] = b.y; ring[s][6] = b.z; ring[s][7] = b.w;
                } else {
                    #pragma unroll
                    for (int t = 0; t < 8; ++t) ring[s][t] = NEG_I;
                }
            }

            int v[8];
            float acc[8];

            // ---- k = 3 ----
            #pragma unroll
            for (int j = 0; j < 8; ++j)
                v[j] = __vimax3_s32(ring[(u + 7) & 7][j], ring[u][j],
                                    ring[(u + 1) & 7][j]);
            {
                int L = __shfl_up_sync  (FULL, v[7], 1); if (l0)  L = NEG_I;
                int R = __shfl_down_sync(FULL, v[0], 1); if (l31) R = NEG_I;
                int m0 = __vimax3_s32(L, v[0], v[1]);
                int m7 = __vimax3_s32(v[6], v[7], R);
                acc[0] = w3 * __log2f(__int_as_float(m0));
                #pragma unroll
                for (int j = 1; j < 7; ++j)
                    acc[j] = w3 * __log2f(__int_as_float(
                                 __vimax3_s32(v[j - 1], v[j], v[j + 1])));
                acc[7] = w3 * __log2f(__int_as_float(m7));
            }

            // ---- k = 5 ----
            #pragma unroll
            for (int j = 0; j < 8; ++j)
                v[j] = __vimax3_s32(v[j], ring[(u + 6) & 7][j],
                                    ring[(u + 2) & 7][j]);
            {
                int p01 = imax2(v[0], v[1]), p23 = imax2(v[2], v[3]);
                int p45 = imax2(v[4], v[5]), p67 = imax2(v[6], v[7]);
                int Lp = __shfl_up_sync  (FULL, p67, 1);
                int L7 = __shfl_up_sync  (FULL, v[7], 1);
                int R0 = __shfl_down_sync(FULL, v[0], 1);
                int Rp = __shfl_down_sync(FULL, p01, 1);
                if (l0)  { Lp = NEG_I; L7 = NEG_I; }
                if (l31) { R0 = NEG_I; Rp = NEG_I; }
                int m[8];
                m[0] = __vimax3_s32(Lp,  p01, v[2]);
                m[1] = __vimax3_s32(L7,  p01, p23);
                m[2] = __vimax3_s32(p01, p23, v[4]);
                m[3] = __vimax3_s32(v[1], p23, p45);
                m[4] = __vimax3_s32(p23, p45, v[6]);
                m[5] = __vimax3_s32(v[3], p45, p67);
                m[6] = __vimax3_s32(p45, p67, R0);
                m[7] = __vimax3_s32(v[5], p67, Rp);
                #pragma unroll
                for (int j = 0; j < 8; ++j)
                    acc[j] = fmaf(w5, __log2f(__int_as_float(m[j])), acc[j]);
            }

            // ---- k = 7 ----
            #pragma unroll
            for (int j = 0; j < 8; ++j)
                v[j] = __vimax3_s32(v[j], ring[(u + 5) & 7][j],
                                    ring[(u + 3) & 7][j]);
            {
                int p01 = imax2(v[0], v[1]), p23 = imax2(v[2], v[3]);
                int p45 = imax2(v[4], v[5]), p67 = imax2(v[6], v[7]);
                int a03 = imax2(p01, p23),   a47 = imax2(p45, p67);
                int suf3 = imax2(v[5], p67); // cols 5..7
                int pre3 = imax2(p01, v[2]); // cols 0..2
                int Ls  = __shfl_up_sync  (FULL, suf3, 1);
                int Lq  = __shfl_up_sync  (FULL, p67, 1);
                int L7v = __shfl_up_sync  (FULL, v[7], 1);
                int R0v = __shfl_down_sync(FULL, v[0], 1);
                int Rq  = __shfl_down_sync(FULL, p01, 1);
                int Rp3 = __shfl_down_sync(FULL, pre3, 1);
                if (l0)  { Ls = NEG_I; Lq = NEG_I; L7v = NEG_I; }
                if (l31) { R0v = NEG_I; Rq = NEG_I; Rp3 = NEG_I; }
                int m[8];
                m[0] = imax2(Ls, a03);               // -3..3
                m[1] = __vimax3_s32(Lq,  a03, v[4]); // -2..4
                m[2] = __vimax3_s32(L7v, a03, p45);  // -1..5
                m[3] = __vimax3_s32(a03, p45, v[6]); //  0..6
                m[4] = __vimax3_s32(v[1], p23, a47); //  1..7
                m[5] = __vimax3_s32(p23, a47, R0v);  //  2..8
                m[6] = __vimax3_s32(v[3], a47, Rq);  //  3..9
                m[7] = imax2(a47, Rp3);              //  4..10
                #pragma unroll
                for (int j = 0; j < 8; ++j)
                    acc[j] = fmaf(w7, __log2f(__int_as_float(m[j])), acc[j]);
            }

            float* dp = dst + y * WW;
            ((float4*)dp)[0] = make_float4(acc[0], acc[1], acc[2], acc[3]);
            ((float4*)dp)[1] = make_float4(acc[4], acc[5], acc[6], acc[7]);
        }
    }
}

extern "C" void kernel_launch(void* const* d_in, const int* in_sizes, int n_in,
                              void* d_out, int out_size)
{
    const int* x = (const int*)d_in[0];
    float* out = (float*)d_out;

    const int planes = in_sizes[0] / (HH * WW);     // 512

    // Closed-form OLS slope weights (double on host); fold in log10(2).
    double l3 = log10(3.0), l5 = log10(5.0), l7 = log10(7.0);
    double mean = (l3 + l5 + l7) / 3.0;
    double c3 = l3 - mean, c5 = l5 - mean, c7 = l7 - mean;
    double s = c3 * c3 + c5 * c5 + c7 * c7;
    double L10_2 = 0.30102999566398119521;
    float w3 = (float)((c3 / s) * L10_2);
    float w5 = (float)((c5 / s) * L10_2);
    float w7 = (float)((c7 / s) * L10_2);

    const int tasks = planes * (HH / RPB);          // 4096
    dim3 grid(tasks);                               // one warp per block
    dim3 block(THREADS);
    holder_kernel<<<grid, block>>>(x, out, w3, w5, w7);
}